// round 6
// baseline (speedup 1.0000x reference)
#include <cuda_runtime.h>
#include <cuda_fp16.h>

// HashGridEncoder2D: L=16, F=2, N=1048576, T=524288. fp16 tables scaled by 4096.
// Levels 0..4  : plain fp16 table staged in SMEM per block (random LDS, no L1 lines)
// Levels 5..11 : quad-packed fp16, one 16B LDG per lookup
// Levels 12..15: hashed (prime 131101, mod 2^19), 16B group-of-4 loads + weight scatter
// Block = 256 threads = 8 slot-warps x 32 points, iterated 8x -> 256 points/block.

#define NPTS    1048576
#define TSIZE   524288
#define TMASK   (TSIZE - 1)
#define HPRIME  131101
#define QT2     653067                 // sum of res^2 over dense levels 5..11
#define HBASE   663817                 // float2 index where hashed tables start
#define NCOARSE 7109                   // entries of levels 0..4 (lat[0:7109))
#define NC_PAD  7112                   // padded to 16B multiple
#define NC_VEC  (NC_PAD / 4)           // 1778 float4s
#define RPTOTAL (QT2 + TSIZE + NC_VEC)
#define SCALE_F     4096.0f
#define INV_SCALE_F (1.0f / 4096.0f)

__constant__ int c_res[16] = {16, 22, 30, 42, 58, 80, 111, 153,
                              212, 294, 406, 561, 776, 1072, 1482, 2048};
__constant__ int c_off[16] = {0, 289, 818, 1779, 3628, 7109, 13670, 26214,
                              49930, 95299, 182324, 347973,
                              663817, 1188105, 1712393, 2236681};
// quad-cell offsets for dense levels 5..11
__constant__ int c_qoff2[7] = {0, 6400, 18721, 42130, 87074, 173510, 338346};
__constant__ int c_res2[7]  = {80, 111, 153, 212, 294, 406, 561};
__constant__ int c_off2[7]  = {7109, 13670, 26214, 49930, 95299, 182324, 347973};

// 10.4 MB: dense cell (l,x,y), l=5..11 -> {v00,v01,v10,v11} as 4 half2 (16B).
__device__ __align__(16) __half2 g_qh[(size_t)QT2 * 4];
// 8.4 MB: 16B-aligned fp16 mirror of the 4 hashed level tables.
__device__ __align__(16) __half2 g_hh[4 * TSIZE];
// 28.4 KB: fp16 copy of coarse tables (levels 0..4 contiguous in lat).
__device__ __align__(16) float4 g_ch4[NC_VEC];

__device__ __forceinline__ __half2 sc_h2(float2 v) {
    return __floats2half2_rn(v.x * SCALE_F, v.y * SCALE_F);
}

__global__ void __launch_bounds__(256)
repack_kernel(const float2* __restrict__ lat)
{
    int c = blockIdx.x * blockDim.x + threadIdx.x;
    if (c >= RPTOTAL) return;

    if (c >= QT2 + TSIZE) {
        // coarse table copy: 4 entries/thread (pad entries read valid lat data)
        int base = (c - (QT2 + TSIZE)) * 4;
        __half2 h0 = sc_h2(lat[base + 0]);
        __half2 h1 = sc_h2(lat[base + 1]);
        __half2 h2 = sc_h2(lat[base + 2]);
        __half2 h3 = sc_h2(lat[base + 3]);
        float4 v;
        ((__half2*)&v)[0] = h0; ((__half2*)&v)[1] = h1;
        ((__half2*)&v)[2] = h2; ((__half2*)&v)[3] = h3;
        g_ch4[base >> 2] = v;
        return;
    }

    if (c >= QT2) {
        // hashed tables contiguous in lat: copy 4 entries/thread, fp16+scale
        int base = (c - QT2) * 4;
        __half2 h0 = sc_h2(lat[HBASE + base + 0]);
        __half2 h1 = sc_h2(lat[HBASE + base + 1]);
        __half2 h2 = sc_h2(lat[HBASE + base + 2]);
        __half2 h3 = sc_h2(lat[HBASE + base + 3]);
        float4 v;
        ((__half2*)&v)[0] = h0; ((__half2*)&v)[1] = h1;
        ((__half2*)&v)[2] = h2; ((__half2*)&v)[3] = h3;
        *(float4*)(g_hh + base) = v;
        return;
    }

    // quad build for levels 5..11
    int li = 0;
#pragma unroll
    for (int i = 1; i < 7; i++) li += (c >= c_qoff2[i]);

    int local = c - c_qoff2[li];
    int res   = c_res2[li];
    int x     = local / res;
    int y     = local - x * res;
    int base  = c_off2[li] + x * res + y;

    __half2 h00 = sc_h2(lat[base]);
    __half2 h01 = sc_h2(lat[base + 1]);
    __half2 h10 = sc_h2(lat[base + res]);
    __half2 h11 = sc_h2(lat[base + res + 1]);

    float4 v;
    ((__half2*)&v)[0] = h00; ((__half2*)&v)[1] = h01;
    ((__half2*)&v)[2] = h10; ((__half2*)&v)[3] = h11;
    *(float4*)(g_qh + (size_t)c * 4) = v;
}

__global__ void __launch_bounds__(256)
hashgrid2d_kernel(const float2* __restrict__ uv,
                  float4* __restrict__ out)
{
    __shared__ float4 s_tab4[NC_VEC];   // 28.4 KB coarse table
    __shared__ float2 s_uv[256];        // 2 KB
    __shared__ float4 s_tr[256];        // 4 KB transpose buffer

    const __half2* s_tab = (const __half2*)s_tab4;

    int tid = threadIdx.x;
    int w   = tid >> 5;          // slot: levels {2w, 2w+1}
    int ln  = tid & 31;
    int n0  = blockIdx.x * 256;

    // stage coarse table + uv
#pragma unroll
    for (int i = tid; i < NC_VEC; i += 256) s_tab4[i] = g_ch4[i];
    s_uv[tid] = __ldg(&uv[n0 + tid]);
    __syncthreads();

#pragma unroll 1
    for (int it = 0; it < 8; it++) {
        int pbase = it * 32;
        float2 p = s_uv[pbase + ln];

        float r0, r1, r2, r3;

        if (w < 6) {
            float rr[4];
#pragma unroll
            for (int k = 0; k < 2; k++) {
                int lvl = 2 * w + k;
                int res = c_res[lvl];

                float fres = (float)res;
                float sx = p.x * fres;
                float sy = p.y * fres;
                float fx = floorf(sx);
                float fy = floorf(sy);
                int   x0 = (int)fx;
                int   y0 = (int)fy;
                float px = sx - fx;
                float py = sy - fy;

                float2 v00, v01, v10, v11;
                if (lvl < 5) {
                    // coarse: SMEM lookup
                    int bi = c_off[lvl] + x0 * res + y0;
                    v00 = __half22float2(s_tab[bi]);
                    v01 = __half22float2(s_tab[bi + 1]);
                    v10 = __half22float2(s_tab[bi + res]);
                    v11 = __half22float2(s_tab[bi + res + 1]);
                } else {
                    // fine dense: one 16B quad LDG
                    float4 raw = *(const float4*)(g_qh +
                        (size_t)(c_qoff2[lvl - 5] + x0 * res + y0) * 4);
                    const __half2* h = (const __half2*)&raw;
                    v00 = __half22float2(h[0]);
                    v01 = __half22float2(h[1]);
                    v10 = __half22float2(h[2]);
                    v11 = __half22float2(h[3]);
                }

                float qx = 1.0f - px;
                float qy = 1.0f - py;
                float w00 = qx * qy;
                float w01 = qx * py;
                float w10 = px * qy;
                float w11 = px * py;

                rr[2 * k + 0] = v00.x * w00 + v01.x * w01 + v10.x * w10 + v11.x * w11;
                rr[2 * k + 1] = v00.y * w00 + v01.y * w01 + v10.y * w10 + v11.y * w11;
            }
            r0 = rr[0]; r1 = rr[1]; r2 = rr[2]; r3 = rr[3];
        } else {
            float rr[4];
#pragma unroll
            for (int k = 0; k < 2; k++) {
                int l = 12 + (w - 6) * 2 + k;

                float fres = (float)c_res[l];
                float sx = p.x * fres;
                float sy = p.y * fres;
                float fx = floorf(sx);
                float fy = floorf(sy);
                int   x0 = (int)fx;
                int   y0 = (int)fy;
                float px = sx - fx;
                float py = sy - fy;

                float qx = 1.0f - px;
                float qy = 1.0f - py;

                const __half2* H = g_hh + (size_t)(l - 12) * TSIZE;

                int hy0 = y0 * HPRIME;
                int hy1 = hy0 + HPRIME;
                int i0  = (x0 ^ hy0) & TMASK;
                int i1  = (x0 ^ hy1) & TMASK;

                float4 raw0 = *(const float4*)(H + (i0 & ~3));
                float4 raw1 = *(const float4*)(H + (i1 & ~3));
                const __half2* v0 = (const __half2*)&raw0;
                const __half2* v1 = (const __half2*)&raw1;

                int  d   = ((x0 + 1) ^ x0) & 3;        // 1 or 3
                bool ing = (x0 & 3) != 3;              // x0+1 in same 16B group?
                float wpx = ing ? px : 0.0f;

                int pA0 = i0 & 3, pB0 = pA0 ^ d;
                int pA1 = i1 & 3, pB1 = pA1 ^ d;

                float e0x = 0.f, e0y = 0.f, e1x = 0.f, e1y = 0.f;
#pragma unroll
                for (int t = 0; t < 4; t++) {
                    float wt0 = (t == pA0) ? qx : ((t == pB0) ? wpx : 0.0f);
                    float wt1 = (t == pA1) ? qx : ((t == pB1) ? wpx : 0.0f);
                    float2 a = __half22float2(v0[t]);
                    float2 b = __half22float2(v1[t]);
                    e0x += wt0 * a.x; e0y += wt0 * a.y;
                    e1x += wt1 * b.x; e1y += wt1 * b.y;
                }

                if (!ing) {
                    int x1 = x0 + 1;
                    float2 f0 = __half22float2(H[(x1 ^ hy0) & TMASK]);
                    float2 f1 = __half22float2(H[(x1 ^ hy1) & TMASK]);
                    e0x += px * f0.x; e0y += px * f0.y;
                    e1x += px * f1.x; e1y += px * f1.y;
                }

                rr[2 * k + 0] = qy * e0x + py * e1x;
                rr[2 * k + 1] = qy * e0y + py * e1y;
            }
            r0 = rr[0]; r1 = rr[1]; r2 = rr[2]; r3 = rr[3];
        }

        r0 *= INV_SCALE_F; r1 *= INV_SCALE_F; r2 *= INV_SCALE_F; r3 *= INV_SCALE_F;

        // XOR-swizzled transpose: conflict-free STS/LDS, coalesced STG
        s_tr[ln * 8 + (w ^ (ln & 7))] = make_float4(r0, r1, r2, r3);
        __syncthreads();

        int jj = tid & 7;
        int ll = tid >> 3;
        out[(size_t)(n0 + pbase) * 8 + tid] = s_tr[ll * 8 + (jj ^ (ll & 7))];
        __syncthreads();
    }
}

extern "C" void kernel_launch(void* const* d_in, const int* in_sizes, int n_in,
                              void* d_out, int out_size)
{
    const float2* uv  = (const float2*)d_in[0];
    const float2* lat = (const float2*)d_in[1];
    float4*       out = (float4*)d_out;

    repack_kernel<<<(RPTOTAL + 255) / 256, 256>>>(lat);

    hashgrid2d_kernel<<<NPTS / 256, 256>>>(uv, out);
}